// round 5
// baseline (speedup 1.0000x reference)
#include <cuda_runtime.h>

#define B_    128
#define T_    4096
#define FEAT_ 64
#define HID_  24
#define G3_   72   // 3 * HID

// Scratch for precomputed GRU1 input gates: [B, T, 72]  (~151 MB)
__device__ float g_xg1[(size_t)B_ * T_ * G3_];

// ---------------------------------------------------------------------------
// Kernel 1: grouped causal conv (k=3, groups=4) + LayerNorm + xg1 GEMM
// grid: (T/128, B), block: 128 threads (one thread per timestep)
// ---------------------------------------------------------------------------
__global__ void __launch_bounds__(128) pre_kernel(
    const float* __restrict__ x,       // [B, T, 64]
    const float* __restrict__ conv_w,  // [64, 16, 3]
    const float* __restrict__ conv_b,  // [64]
    const float* __restrict__ gamma,   // [64]
    const float* __restrict__ beta,    // [64]
    const float* __restrict__ w_ih1,   // [72, 64]
    const float* __restrict__ b_ih1)   // [72]
{
    extern __shared__ float sm[];
    float* xs = sm;                 // 130 * 68 (rows padded to 68 floats, 16B-aligned)
    float* cw = xs + 130 * 68;      // 3072
    float* cb = cw + 3072;          // 64
    float* gm = cb + 64;            // 64
    float* bt = gm + 64;            // 64
    float* wi = bt + 64;            // 4608
    float* b1 = wi + 4608;          // 72

    const int b   = blockIdx.y;
    const int t0  = blockIdx.x * 128;
    const int tid = threadIdx.x;

    // cooperative loads
    const float* xb = x + (size_t)b * T_ * FEAT_;
    for (int i = tid; i < 130 * 64; i += 128) {
        int r = i >> 6, f = i & 63;
        int t = t0 - 2 + r;                       // row r holds time t0-2+r (causal pad)
        xs[r * 68 + f] = (t >= 0) ? xb[(size_t)t * 64 + f] : 0.f;
    }
    for (int i = tid; i < 3072; i += 128) cw[i] = conv_w[i];
    for (int i = tid; i < 4608; i += 128) wi[i] = w_ih1[i];
    if (tid < 64) { cb[tid] = conv_b[tid]; gm[tid] = gamma[tid]; bt[tid] = beta[tid]; }
    if (tid < 72) b1[tid] = b_ih1[tid];
    __syncthreads();

    // grouped causal conv: y[f] = cb[f] + sum_{c,k} w[f,c,k] * x[t-2+k, g*16+c]
    float y[64];
    #pragma unroll
    for (int g = 0; g < 4; g++) {
        float xk[3][16];
        #pragma unroll
        for (int k = 0; k < 3; k++) {
            const float4* p = (const float4*)&xs[(tid + k) * 68 + g * 16];
            #pragma unroll
            for (int q = 0; q < 4; q++) {
                float4 v = p[q];
                xk[k][4*q+0] = v.x; xk[k][4*q+1] = v.y;
                xk[k][4*q+2] = v.z; xk[k][4*q+3] = v.w;
            }
        }
        #pragma unroll
        for (int fo = 0; fo < 16; fo++) {
            const int f = g * 16 + fo;
            float acc = cb[f];
            const float4* wp = (const float4*)&cw[f * 48];   // layout [c][k], c*3+k
            #pragma unroll
            for (int j = 0; j < 12; j++) {
                float4 w4 = wp[j];
                acc = fmaf(w4.x, xk[(4*j+0)%3][(4*j+0)/3], acc);
                acc = fmaf(w4.y, xk[(4*j+1)%3][(4*j+1)/3], acc);
                acc = fmaf(w4.z, xk[(4*j+2)%3][(4*j+2)/3], acc);
                acc = fmaf(w4.w, xk[(4*j+3)%3][(4*j+3)/3], acc);
            }
            y[f] = acc;
        }
    }

    // LayerNorm over 64 features (biased variance, eps 1e-5)
    float s = 0.f, s2 = 0.f;
    #pragma unroll
    for (int f = 0; f < 64; f++) { s += y[f]; s2 = fmaf(y[f], y[f], s2); }
    float mean = s * (1.f / 64.f);
    float var  = s2 * (1.f / 64.f) - mean * mean;
    float rs   = rsqrtf(var + 1e-5f);
    #pragma unroll
    for (int f = 0; f < 64; f++) y[f] = (y[f] - mean) * rs * gm[f] + bt[f];

    // xg1[o] = b_ih1[o] + sum_c y[c] * w_ih1[o][c]
    float* outp = g_xg1 + ((size_t)b * T_ + (t0 + tid)) * G3_;
    for (int o = 0; o < 72; o++) {
        float a0 = 0, a1 = 0, a2 = 0, a3 = 0;
        const float4* wp = (const float4*)&wi[o * 64];
        #pragma unroll
        for (int c = 0; c < 16; c++) {
            float4 w4 = wp[c];
            a0 = fmaf(w4.x, y[4*c+0], a0);
            a1 = fmaf(w4.y, y[4*c+1], a1);
            a2 = fmaf(w4.z, y[4*c+2], a2);
            a3 = fmaf(w4.w, y[4*c+3], a3);
        }
        outp[o] = ((a0 + a1) + (a2 + a3)) + b1[o];
    }
}

// ---------------------------------------------------------------------------
// Kernel 2: fused GRU1 + GRU2 + FC head + confidence, one CTA per batch.
// Threads 0..71: recurrent mat-vecs (weights in registers).
// Threads 0..23: gate nonlinearities + state update.
// Threads 96..127 (warp 3): FC + std + output stores, off the critical path.
// ---------------------------------------------------------------------------
__device__ __forceinline__ float fast_sigmoid(float v) {
    float e = __expf(-v);
    return __fdividef(1.f, 1.f + e);
}
__device__ __forceinline__ float fast_tanh(float v) {
    float e = __expf(2.f * v);
    return 1.f - __fdividef(2.f, e + 1.f);
}

__global__ void __launch_bounds__(128, 1) gru_kernel(
    const float* __restrict__ h1_0, const float* __restrict__ h2_0,
    const float* __restrict__ w_hh1, const float* __restrict__ b_hh1,
    const float* __restrict__ w_ih2, const float* __restrict__ w_hh2,
    const float* __restrict__ b_ih2, const float* __restrict__ b_hh2,
    const float* __restrict__ fc_w,  const float* __restrict__ fc_b,
    float* __restrict__ out_noise, float* __restrict__ out_h1,
    float* __restrict__ out_h2,    float* __restrict__ out_conf,
    int write_extra)
{
    __shared__ __align__(16) float h1s[24];
    __shared__ __align__(16) float h2s[24];
    __shared__ float sA[72];
    __shared__ float sB[24];

    const int b   = blockIdx.x;
    const int tid = threadIdx.x;

    // per-thread register weights
    float wh1[24], wi2[24], wh2[24];
    float bh1 = 0.f, bi2 = 0.f, bh2 = 0.f;
    if (tid < 72) {
        #pragma unroll
        for (int k = 0; k < 24; k++) {
            wh1[k] = w_hh1[tid * 24 + k];
            wi2[k] = w_ih2[tid * 24 + k];
            wh2[k] = w_hh2[tid * 24 + k];
        }
        bh1 = b_hh1[tid]; bi2 = b_ih2[tid]; bh2 = b_hh2[tid];
    }
    float fw[24]; float fb = 0.f;
    const int lane = tid - 96;
    if (tid >= 96) {
        #pragma unroll
        for (int k = 0; k < 24; k++) fw[k] = fc_w[lane * 24 + k];
        fb = fc_b[lane];
    }
    if (tid < 24) { h1s[tid] = h1_0[b * 24 + tid]; h2s[tid] = h2_0[b * 24 + tid]; }
    __syncthreads();

    const float* xg = g_xg1 + (size_t)b * T_ * G3_;
    // 3-deep register prefetch of xg1 rows (hides DRAM latency)
    float xc = 0.f, xn1 = 0.f, xn2 = 0.f;
    if (tid < 72) {
        xc  = xg[tid];
        xn1 = xg[72 + tid];
        xn2 = xg[144 + tid];
    }

    for (int t = 0; t < T_; t++) {
        float xpref = 0.f;
        if (tid < 72) {
            int tn = t + 3; if (tn > T_ - 1) tn = T_ - 1;
            xpref = __ldg(&xg[(size_t)tn * 72 + tid]);

            // S1: hg1 = w_hh1 @ h1 + b_hh1
            float hv[24];
            #pragma unroll
            for (int q = 0; q < 6; q++) {
                float4 v = ((const float4*)h1s)[q];
                hv[4*q+0] = v.x; hv[4*q+1] = v.y; hv[4*q+2] = v.z; hv[4*q+3] = v.w;
            }
            float a0 = 0, a1 = 0, a2 = 0, a3 = 0;
            #pragma unroll
            for (int k = 0; k < 24; k += 4) {
                a0 = fmaf(wh1[k+0], hv[k+0], a0);
                a1 = fmaf(wh1[k+1], hv[k+1], a1);
                a2 = fmaf(wh1[k+2], hv[k+2], a2);
                a3 = fmaf(wh1[k+3], hv[k+3], a3);
            }
            float hg = bh1 + ((a0 + a1) + (a2 + a3));
            if (tid < 48) sA[tid] = fast_sigmoid(xc + hg);   // r,z pre-activations
            else { sA[tid] = hg; sB[tid - 48] = xc; }         // hn, xn kept separate
        }
        __syncthreads();
        if (tid < 24) { // GRU1 gates + state update
            float r = sA[tid], z = sA[24 + tid];
            float n = fast_tanh(sB[tid] + r * sA[48 + tid]);
            h1s[tid] = (1.f - z) * n + z * h1s[tid];
        }
        __syncthreads();
        if (tid < 72) {
            // S2: xg2 = w_ih2 @ h1_new + b_ih2 ; hg2 = w_hh2 @ h2 + b_hh2
            float hv1[24], hv2[24];
            #pragma unroll
            for (int q = 0; q < 6; q++) {
                float4 v1 = ((const float4*)h1s)[q];
                float4 v2 = ((const float4*)h2s)[q];
                hv1[4*q+0] = v1.x; hv1[4*q+1] = v1.y; hv1[4*q+2] = v1.z; hv1[4*q+3] = v1.w;
                hv2[4*q+0] = v2.x; hv2[4*q+1] = v2.y; hv2[4*q+2] = v2.z; hv2[4*q+3] = v2.w;
            }
            float a0=0, a1=0, a2=0, a3=0, c0=0, c1=0, c2=0, c3=0;
            #pragma unroll
            for (int k = 0; k < 24; k += 4) {
                a0 = fmaf(wi2[k+0], hv1[k+0], a0);
                a1 = fmaf(wi2[k+1], hv1[k+1], a1);
                a2 = fmaf(wi2[k+2], hv1[k+2], a2);
                a3 = fmaf(wi2[k+3], hv1[k+3], a3);
                c0 = fmaf(wh2[k+0], hv2[k+0], c0);
                c1 = fmaf(wh2[k+1], hv2[k+1], c1);
                c2 = fmaf(wh2[k+2], hv2[k+2], c2);
                c3 = fmaf(wh2[k+3], hv2[k+3], c3);
            }
            float xd = bi2 + ((a0 + a1) + (a2 + a3));
            float hd = bh2 + ((c0 + c1) + (c2 + c3));
            if (tid < 48) sA[tid] = fast_sigmoid(xd + hd);
            else { sA[tid] = hd; sB[tid - 48] = xd; }
        }
        __syncthreads();
        if (tid < 24) { // GRU2 gates + state update
            float r = sA[tid], z = sA[24 + tid];
            float n = fast_tanh(sB[tid] + r * sA[48 + tid]);
            h2s[tid] = (1.f - z) * n + z * h2s[tid];
        }
        __syncthreads();

        // warp 3: FC head + stddev + stores (overlaps next step's S1)
        if (tid >= 96) {
            float hv[24];
            #pragma unroll
            for (int q = 0; q < 6; q++) {
                float4 v = ((const float4*)h2s)[q];
                hv[4*q+0] = v.x; hv[4*q+1] = v.y; hv[4*q+2] = v.z; hv[4*q+3] = v.w;
            }
            float a0 = 0, a1 = 0, a2 = 0, a3 = 0;
            #pragma unroll
            for (int k = 0; k < 24; k += 4) {
                a0 = fmaf(fw[k+0], hv[k+0], a0);
                a1 = fmaf(fw[k+1], hv[k+1], a1);
                a2 = fmaf(fw[k+2], hv[k+2], a2);
                a3 = fmaf(fw[k+3], hv[k+3], a3);
            }
            float o = fb + ((a0 + a1) + (a2 + a3));
            out_noise[((size_t)b * T_ + t) * 32 + lane] = o;
            if (write_extra) {
                float su = o, sq = o * o;
                #pragma unroll
                for (int m = 16; m >= 1; m >>= 1) {
                    su += __shfl_xor_sync(0xffffffffu, su, m);
                    sq += __shfl_xor_sync(0xffffffffu, sq, m);
                }
                if (lane == 0) {
                    float ss = fmaxf(sq - su * su * (1.f / 32.f), 0.f);
                    float sd = sqrtf(ss * (1.f / 31.f));   // ddof = 1
                    out_conf[(size_t)b * T_ + t] = __fdividef(1.f, 1.f + sd);
                }
            }
        }
        if (tid < 72) { xc = xn1; xn1 = xn2; xn2 = xpref; }
    }

    if (write_extra && tid < 24) {
        out_h1[b * 24 + tid] = h1s[tid];
        out_h2[b * 24 + tid] = h2s[tid];
    }
}

// ---------------------------------------------------------------------------
extern "C" void kernel_launch(void* const* d_in, const int* in_sizes, int n_in,
                              void* d_out, int out_size)
{
    const float* x      = (const float*)d_in[0];
    const float* h1     = (const float*)d_in[1];
    const float* h2     = (const float*)d_in[2];
    const float* conv_w = (const float*)d_in[3];
    const float* conv_b = (const float*)d_in[4];
    const float* gamma  = (const float*)d_in[5];
    const float* beta   = (const float*)d_in[6];
    const float* w_ih1  = (const float*)d_in[7];
    const float* w_hh1  = (const float*)d_in[8];
    const float* b_ih1  = (const float*)d_in[9];
    const float* b_hh1  = (const float*)d_in[10];
    const float* w_ih2  = (const float*)d_in[11];
    const float* w_hh2  = (const float*)d_in[12];
    const float* b_ih2  = (const float*)d_in[13];
    const float* b_hh2  = (const float*)d_in[14];
    const float* fc_w   = (const float*)d_in[15];
    const float* fc_b   = (const float*)d_in[16];

    float* out = (float*)d_out;
    const size_t NOISE = (size_t)B_ * T_ * 32;                       // 16,777,216
    const size_t FULL  = NOISE + 2 * (size_t)B_ * HID_ + (size_t)B_ * T_;
    int extra = ((size_t)out_size >= FULL) ? 1 : 0;
    float* o_h1   = out + NOISE;
    float* o_h2   = o_h1 + B_ * HID_;
    float* o_conf = o_h2 + B_ * HID_;

    const int SMEM = (130 * 68 + 3072 + 64 * 3 + 4608 + 72) * (int)sizeof(float); // 67,136 B
    cudaFuncSetAttribute(pre_kernel, cudaFuncAttributeMaxDynamicSharedMemorySize, SMEM);

    pre_kernel<<<dim3(T_ / 128, B_), 128, SMEM>>>(x, conv_w, conv_b, gamma, beta,
                                                  w_ih1, b_ih1);
    gru_kernel<<<B_, 128>>>(h1, h2, w_hh1, b_hh1, w_ih2, w_hh2, b_ih2, b_hh2,
                            fc_w, fc_b, out, o_h1, o_h2, o_conf, extra);
}

// round 6
// speedup vs baseline: 1.2041x; 1.2041x over previous
#include <cuda_runtime.h>

#define B_    128
#define T_    4096
#define FEAT_ 64
#define HID_  24
#define G3_   72   // 3 * HID

// Scratch for precomputed GRU1 input gates: [B, T, 72]  (~151 MB)
__device__ float g_xg1[(size_t)B_ * T_ * G3_];

// ---------------------------------------------------------------------------
// Packed f32x2 FMA helpers (PTX 8.6, sm_100+)
// ---------------------------------------------------------------------------
#define FMA2(acc, a, b) \
    asm("fma.rn.f32x2 %0, %1, %2, %0;" : "+l"(acc) : "l"(a), "l"(b))

__device__ __forceinline__ float hsum2(unsigned long long v) {
    float lo, hi;
    asm("mov.b64 {%0, %1}, %2;" : "=f"(lo), "=f"(hi) : "l"(v));
    return lo + hi;
}
__device__ __forceinline__ float fast_sigmoid(float v) {
    return __fdividef(1.f, 1.f + __expf(-v));
}
__device__ __forceinline__ float fast_tanh(float v) {
    return 1.f - __fdividef(2.f, __expf(2.f * v) + 1.f);
}

// ---------------------------------------------------------------------------
// Kernel 1: grouped causal conv (k=3, groups=4) + LayerNorm + xg1 GEMM
// grid: (T/128, B), block: 128 threads (one thread per timestep)
// ---------------------------------------------------------------------------
__global__ void __launch_bounds__(128) pre_kernel(
    const float* __restrict__ x,       // [B, T, 64]
    const float* __restrict__ conv_w,  // [64, 16, 3]
    const float* __restrict__ conv_b,  // [64]
    const float* __restrict__ gamma,   // [64]
    const float* __restrict__ beta,    // [64]
    const float* __restrict__ w_ih1,   // [72, 64]
    const float* __restrict__ b_ih1)   // [72]
{
    extern __shared__ float sm[];
    float* xs = sm;                 // 130 * 68 (rows padded to 68 floats)
    float* cw = xs + 130 * 68;      // 3072
    float* cb = cw + 3072;          // 64
    float* gm = cb + 64;            // 64
    float* bt = gm + 64;            // 64
    float* wi = bt + 64;            // 4608
    float* b1 = wi + 4608;          // 72

    const int b   = blockIdx.y;
    const int t0  = blockIdx.x * 128;
    const int tid = threadIdx.x;

    const float* xb = x + (size_t)b * T_ * FEAT_;
    for (int i = tid; i < 130 * 64; i += 128) {
        int r = i >> 6, f = i & 63;
        int t = t0 - 2 + r;
        xs[r * 68 + f] = (t >= 0) ? xb[(size_t)t * 64 + f] : 0.f;
    }
    for (int i = tid; i < 3072; i += 128) cw[i] = conv_w[i];
    for (int i = tid; i < 4608; i += 128) wi[i] = w_ih1[i];
    if (tid < 64) { cb[tid] = conv_b[tid]; gm[tid] = gamma[tid]; bt[tid] = beta[tid]; }
    if (tid < 72) b1[tid] = b_ih1[tid];
    __syncthreads();

    float y[64];
    #pragma unroll
    for (int g = 0; g < 4; g++) {
        float xk[3][16];
        #pragma unroll
        for (int k = 0; k < 3; k++) {
            const float4* p = (const float4*)&xs[(tid + k) * 68 + g * 16];
            #pragma unroll
            for (int q = 0; q < 4; q++) {
                float4 v = p[q];
                xk[k][4*q+0] = v.x; xk[k][4*q+1] = v.y;
                xk[k][4*q+2] = v.z; xk[k][4*q+3] = v.w;
            }
        }
        #pragma unroll
        for (int fo = 0; fo < 16; fo++) {
            const int f = g * 16 + fo;
            float acc = cb[f];
            const float4* wp = (const float4*)&cw[f * 48];
            #pragma unroll
            for (int j = 0; j < 12; j++) {
                float4 w4 = wp[j];
                acc = fmaf(w4.x, xk[(4*j+0)%3][(4*j+0)/3], acc);
                acc = fmaf(w4.y, xk[(4*j+1)%3][(4*j+1)/3], acc);
                acc = fmaf(w4.z, xk[(4*j+2)%3][(4*j+2)/3], acc);
                acc = fmaf(w4.w, xk[(4*j+3)%3][(4*j+3)/3], acc);
            }
            y[f] = acc;
        }
    }

    float s = 0.f, s2 = 0.f;
    #pragma unroll
    for (int f = 0; f < 64; f++) { s += y[f]; s2 = fmaf(y[f], y[f], s2); }
    float mean = s * (1.f / 64.f);
    float var  = s2 * (1.f / 64.f) - mean * mean;
    float rs   = rsqrtf(var + 1e-5f);
    #pragma unroll
    for (int f = 0; f < 64; f++) y[f] = (y[f] - mean) * rs * gm[f] + bt[f];

    float* outp = g_xg1 + ((size_t)b * T_ + (t0 + tid)) * G3_;
    for (int o = 0; o < 72; o++) {
        float a0 = 0, a1 = 0, a2 = 0, a3 = 0;
        const float4* wp = (const float4*)&wi[o * 64];
        #pragma unroll
        for (int c = 0; c < 16; c++) {
            float4 w4 = wp[c];
            a0 = fmaf(w4.x, y[4*c+0], a0);
            a1 = fmaf(w4.y, y[4*c+1], a1);
            a2 = fmaf(w4.z, y[4*c+2], a2);
            a3 = fmaf(w4.w, y[4*c+3], a3);
        }
        outp[o] = ((a0 + a1) + (a2 + a3)) + b1[o];
    }
}

// ---------------------------------------------------------------------------
// Kernel 2: layer-pipelined GRU stack. One CTA per batch, 4 warps = 4 pipeline
// stages on 4 SMSPs, ONE __syncthreads per tick:
//   warp 0: GRU1 recurrent  -> h1(tau)            (ticks [0, T))
//   warp 1: xg2 = Wih2@h1   for step tau-1        (ticks [1, T])
//   warp 2: GRU2 recurrent  -> h2(tau-2)          (ticks [2, T+1])
//   warp 3: FC head         for step tau-3        (ticks [3, T+2])
// All GEMVs use packed fma.rn.f32x2 with weights held in registers.
// ---------------------------------------------------------------------------
__global__ void __launch_bounds__(128, 1) gru_kernel(
    const float* __restrict__ h1_0, const float* __restrict__ h2_0,
    const float* __restrict__ w_hh1, const float* __restrict__ b_hh1,
    const float* __restrict__ w_ih2, const float* __restrict__ w_hh2,
    const float* __restrict__ b_ih2, const float* __restrict__ b_hh2,
    const float* __restrict__ fc_w,  const float* __restrict__ fc_b,
    float* __restrict__ out_noise, float* __restrict__ out_h1,
    float* __restrict__ out_h2, int write_extra)
{
    __shared__ __align__(16) float h1buf[2][24];
    __shared__ __align__(16) float h2buf[2][24];
    __shared__ __align__(16) float xg2buf[2][72];

    const int b    = blockIdx.x;
    const int tid  = threadIdx.x;
    const int w    = tid >> 5;
    const int lane = tid & 31;

    // Per-warp register weights, packed as f32x2 pairs.
    unsigned long long wr[12], wz[12], wn[12];
    float br = 0.f, bz = 0.f, bn = 0.f;
    {
        const float* W  = (w == 0) ? w_hh1 : (w == 1) ? w_ih2 : (w == 2) ? w_hh2 : fc_w;
        const float* Bv = (w == 0) ? b_hh1 : (w == 1) ? b_ih2 : (w == 2) ? b_hh2 : fc_b;
        if (w < 3) {
            if (lane < 24) {
                const unsigned long long* Wr = (const unsigned long long*)(W + lane * 24);
                const unsigned long long* Wz = (const unsigned long long*)(W + (24 + lane) * 24);
                const unsigned long long* Wn = (const unsigned long long*)(W + (48 + lane) * 24);
                #pragma unroll
                for (int j = 0; j < 12; j++) { wr[j] = Wr[j]; wz[j] = Wz[j]; wn[j] = Wn[j]; }
                br = Bv[lane]; bz = Bv[24 + lane]; bn = Bv[48 + lane];
            }
        } else {
            const unsigned long long* Wf = (const unsigned long long*)(W + lane * 24);
            #pragma unroll
            for (int j = 0; j < 12; j++) wr[j] = Wf[j];
            br = Bv[lane];
        }
    }

    if (tid < 24) {
        h1buf[1][tid] = h1_0[b * 24 + tid];
        h2buf[1][tid] = h2_0[b * 24 + tid];
    }

    // 3-deep register prefetch queue of xg1 gate triples (warp 0 only)
    const float* xg = g_xg1 + (size_t)b * T_ * G3_;
    float qr[3], qz[3], qn[3];
    if (w == 0 && lane < 24) {
        #pragma unroll
        for (int d = 0; d < 3; d++) {
            qr[d] = __ldg(&xg[(size_t)d * 72 + lane]);
            qz[d] = __ldg(&xg[(size_t)d * 72 + 24 + lane]);
            qn[d] = __ldg(&xg[(size_t)d * 72 + 48 + lane]);
        }
    }
    __syncthreads();

    for (int tau = 0; tau < T_ + 3; tau++) {
        const int ws = tau & 1, rs = ws ^ 1;
        if (w == 0) {
            if (lane < 24 && tau < T_) {
                int tp = tau + 3; if (tp > T_ - 1) tp = T_ - 1;
                float pr = __ldg(&xg[(size_t)tp * 72 + lane]);
                float pz = __ldg(&xg[(size_t)tp * 72 + 24 + lane]);
                float pn = __ldg(&xg[(size_t)tp * 72 + 48 + lane]);

                unsigned long long h64[12];
                const ulonglong2* hp = (const ulonglong2*)h1buf[rs];
                #pragma unroll
                for (int q = 0; q < 6; q++) { ulonglong2 v = hp[q]; h64[2*q] = v.x; h64[2*q+1] = v.y; }
                float hold = h1buf[rs][lane];
                unsigned long long ar = 0ull, az = 0ull, an = 0ull;
                #pragma unroll
                for (int j = 0; j < 12; j++) { FMA2(ar, wr[j], h64[j]); FMA2(az, wz[j], h64[j]); FMA2(an, wn[j], h64[j]); }
                float r = fast_sigmoid(qr[0] + hsum2(ar) + br);
                float z = fast_sigmoid(qz[0] + hsum2(az) + bz);
                float n = fast_tanh(qn[0] + r * (hsum2(an) + bn));
                h1buf[ws][lane] = n + z * (hold - n);
                qr[0] = qr[1]; qr[1] = qr[2]; qr[2] = pr;
                qz[0] = qz[1]; qz[1] = qz[2]; qz[2] = pz;
                qn[0] = qn[1]; qn[1] = qn[2]; qn[2] = pn;
            }
        } else if (w == 1) {
            if (lane < 24 && tau >= 1 && tau <= T_) {
                unsigned long long h64[12];
                const ulonglong2* hp = (const ulonglong2*)h1buf[rs];  // h1(tau-1)
                #pragma unroll
                for (int q = 0; q < 6; q++) { ulonglong2 v = hp[q]; h64[2*q] = v.x; h64[2*q+1] = v.y; }
                unsigned long long ar = 0ull, az = 0ull, an = 0ull;
                #pragma unroll
                for (int j = 0; j < 12; j++) { FMA2(ar, wr[j], h64[j]); FMA2(az, wz[j], h64[j]); FMA2(an, wn[j], h64[j]); }
                xg2buf[ws][lane]      = hsum2(ar) + br;
                xg2buf[ws][24 + lane] = hsum2(az) + bz;
                xg2buf[ws][48 + lane] = hsum2(an) + bn;
            }
        } else if (w == 2) {
            if (lane < 24 && tau >= 2 && tau <= T_ + 1) {
                unsigned long long h64[12];
                const ulonglong2* hp = (const ulonglong2*)h2buf[rs];  // h2(tau-3)
                #pragma unroll
                for (int q = 0; q < 6; q++) { ulonglong2 v = hp[q]; h64[2*q] = v.x; h64[2*q+1] = v.y; }
                float hold = h2buf[rs][lane];
                float xr = xg2buf[rs][lane];
                float xz = xg2buf[rs][24 + lane];
                float xn = xg2buf[rs][48 + lane];
                unsigned long long ar = 0ull, az = 0ull, an = 0ull;
                #pragma unroll
                for (int j = 0; j < 12; j++) { FMA2(ar, wr[j], h64[j]); FMA2(az, wz[j], h64[j]); FMA2(an, wn[j], h64[j]); }
                float r = fast_sigmoid(xr + hsum2(ar) + br);
                float z = fast_sigmoid(xz + hsum2(az) + bz);
                float n = fast_tanh(xn + r * (hsum2(an) + bn));
                h2buf[ws][lane] = n + z * (hold - n);
            }
        } else {
            if (tau >= 3) {
                unsigned long long h64[12];
                const ulonglong2* hp = (const ulonglong2*)h2buf[rs];  // h2(tau-3)
                #pragma unroll
                for (int q = 0; q < 6; q++) { ulonglong2 v = hp[q]; h64[2*q] = v.x; h64[2*q+1] = v.y; }
                unsigned long long a = 0ull;
                #pragma unroll
                for (int j = 0; j < 12; j++) FMA2(a, wr[j], h64[j]);
                out_noise[((size_t)b * T_ + (tau - 3)) * 32 + lane] = hsum2(a) + br;
            }
        }
        __syncthreads();
    }

    if (write_extra && tid < 24) {
        out_h1[b * 24 + tid] = h1buf[(T_ - 1) & 1][tid];   // h1(T-1) written at tick T-1
        out_h2[b * 24 + tid] = h2buf[(T_ + 1) & 1][tid];   // h2(T-1) written at tick T+1
    }
}

// ---------------------------------------------------------------------------
// Kernel 3: confidence = 1/(1+std(noise, ddof=1)) over last dim (32).
// One warp per (b,t) row; fully parallel, ~15us.
// ---------------------------------------------------------------------------
__global__ void __launch_bounds__(256) conf_kernel(
    const float* __restrict__ noise, float* __restrict__ conf)
{
    const size_t row = (size_t)blockIdx.x * 8 + (threadIdx.x >> 5);
    const int lane = threadIdx.x & 31;
    float o = noise[row * 32 + lane];
    float su = o, sq = o * o;
    #pragma unroll
    for (int m = 16; m >= 1; m >>= 1) {
        su += __shfl_xor_sync(0xffffffffu, su, m);
        sq += __shfl_xor_sync(0xffffffffu, sq, m);
    }
    if (lane == 0) {
        float ss = fmaxf(sq - su * su * (1.f / 32.f), 0.f);
        float sd = sqrtf(ss * (1.f / 31.f));   // ddof = 1
        conf[row] = __fdividef(1.f, 1.f + sd);
    }
}

// ---------------------------------------------------------------------------
extern "C" void kernel_launch(void* const* d_in, const int* in_sizes, int n_in,
                              void* d_out, int out_size)
{
    const float* x      = (const float*)d_in[0];
    const float* h1     = (const float*)d_in[1];
    const float* h2     = (const float*)d_in[2];
    const float* conv_w = (const float*)d_in[3];
    const float* conv_b = (const float*)d_in[4];
    const float* gamma  = (const float*)d_in[5];
    const float* beta   = (const float*)d_in[6];
    const float* w_ih1  = (const float*)d_in[7];
    const float* w_hh1  = (const float*)d_in[8];
    const float* b_ih1  = (const float*)d_in[9];
    const float* b_hh1  = (const float*)d_in[10];
    const float* w_ih2  = (const float*)d_in[11];
    const float* w_hh2  = (const float*)d_in[12];
    const float* b_ih2  = (const float*)d_in[13];
    const float* b_hh2  = (const float*)d_in[14];
    const float* fc_w   = (const float*)d_in[15];
    const float* fc_b   = (const float*)d_in[16];

    float* out = (float*)d_out;
    const size_t NOISE = (size_t)B_ * T_ * 32;
    const size_t FULL  = NOISE + 2 * (size_t)B_ * HID_ + (size_t)B_ * T_;
    int extra = ((size_t)out_size >= FULL) ? 1 : 0;
    float* o_h1   = out + NOISE;
    float* o_h2   = o_h1 + B_ * HID_;
    float* o_conf = o_h2 + B_ * HID_;

    const int SMEM = (130 * 68 + 3072 + 64 * 3 + 4608 + 72) * (int)sizeof(float);
    cudaFuncSetAttribute(pre_kernel, cudaFuncAttributeMaxDynamicSharedMemorySize, SMEM);

    pre_kernel<<<dim3(T_ / 128, B_), 128, SMEM>>>(x, conv_w, conv_b, gamma, beta,
                                                  w_ih1, b_ih1);
    gru_kernel<<<B_, 128>>>(h1, h2, w_hh1, b_hh1, w_ih2, w_hh2, b_ih2, b_hh2,
                            fc_w, fc_b, out, o_h1, o_h2, extra);
    if (extra) conf_kernel<<<(B_ * T_) / 8, 256>>>(out, o_conf);
}

// round 7
// speedup vs baseline: 1.8894x; 1.5691x over previous
#include <cuda_runtime.h>

#define B_    128
#define T_    4096
#define FEAT_ 64
#define HID_  24
#define G3_   72   // 3 * HID

// Scratch for precomputed GRU1 input gates: [B, T, 72]  (~151 MB)
__device__ float g_xg1[(size_t)B_ * T_ * G3_];

// ---------------------------------------------------------------------------
// Packed f32x2 helpers (PTX 8.6, sm_100+)
// ---------------------------------------------------------------------------
#define FMA2(acc, a, b) \
    asm("fma.rn.f32x2 %0, %1, %2, %0;" : "+l"(acc) : "l"(a), "l"(b))
#define ADD2(d, a, b) \
    asm("add.rn.f32x2 %0, %1, %2;" : "=l"(d) : "l"(a), "l"(b))

__device__ __forceinline__ unsigned long long pk2(float lo, float hi) {
    unsigned long long r;
    asm("mov.b64 %0, {%1, %2};" : "=l"(r) : "f"(lo), "f"(hi));
    return r;
}
__device__ __forceinline__ float hsum2(unsigned long long v) {
    float lo, hi;
    asm("mov.b64 {%0, %1}, %2;" : "=f"(lo), "=f"(hi) : "l"(v));
    return lo + hi;
}
__device__ __forceinline__ float fast_sigmoid(float v) {
    return __fdividef(1.f, 1.f + __expf(-v));
}
__device__ __forceinline__ float fast_tanh(float v) {
    return 1.f - __fdividef(2.f, __expf(2.f * v) + 1.f);
}
__device__ __forceinline__ unsigned smem_u32(const void* p) {
    unsigned a;
    asm("{ .reg .u64 t; cvta.to.shared.u64 t, %1; cvt.u32.u64 %0, t; }"
        : "=r"(a) : "l"(p));
    return a;
}
#define CP_ASYNC16(dst_u32, src_ptr) \
    asm volatile("cp.async.cg.shared.global [%0], [%1], 16;" \
                 :: "r"(dst_u32), "l"(src_ptr))
#define CP_COMMIT()  asm volatile("cp.async.commit_group;")
#define CP_WAIT(N)   asm volatile("cp.async.wait_group %0;" :: "n"(N))

// ---------------------------------------------------------------------------
// Kernel 1: grouped causal conv (k=3, groups=4) + LayerNorm + xg1 GEMM
// grid: (T/128, B), block: 128 threads (one thread per timestep)
// All heavy FMAs packed as f32x2.
// ---------------------------------------------------------------------------
__global__ void __launch_bounds__(128) pre_kernel(
    const float* __restrict__ x,       // [B, T, 64]
    const float* __restrict__ conv_w,  // [64, 16, 3]
    const float* __restrict__ conv_b,  // [64]
    const float* __restrict__ gamma,   // [64]
    const float* __restrict__ beta,    // [64]
    const float* __restrict__ w_ih1,   // [72, 64]
    const float* __restrict__ b_ih1)   // [72]
{
    extern __shared__ float sm[];
    float* xs  = sm;                 // 130 * 68 (rows padded to 68 floats)
    float* cwt = xs + 130 * 68;      // 3072, transposed to [f][k][c]
    float* cb  = cwt + 3072;         // 64
    float* gm  = cb + 64;            // 64
    float* bt  = gm + 64;            // 64
    float* wi  = bt + 64;            // 4608
    float* b1  = wi + 4608;          // 72

    const int b   = blockIdx.y;
    const int t0  = blockIdx.x * 128;
    const int tid = threadIdx.x;

    const float* xb = x + (size_t)b * T_ * FEAT_;
    for (int i = tid; i < 130 * 64; i += 128) {
        int r = i >> 6, f = i & 63;
        int t = t0 - 2 + r;
        xs[r * 68 + f] = (t >= 0) ? xb[(size_t)t * 64 + f] : 0.f;
    }
    // transpose conv weights [f][c][k] -> [f][k][c] so c-pairs are contiguous
    for (int i = tid; i < 3072; i += 128) {
        int f = i / 48, r = i % 48, k = r >> 4, c = r & 15;
        cwt[i] = conv_w[f * 48 + c * 3 + k];
    }
    for (int i = tid; i < 4608; i += 128) wi[i] = w_ih1[i];
    if (tid < 64) { cb[tid] = conv_b[tid]; gm[tid] = gamma[tid]; bt[tid] = beta[tid]; }
    if (tid < 72) b1[tid] = b_ih1[tid];
    __syncthreads();

    float y[64];
    #pragma unroll
    for (int g = 0; g < 4; g++) {
        unsigned long long xk2[3][8];
        #pragma unroll
        for (int k = 0; k < 3; k++) {
            const float4* p = (const float4*)&xs[(tid + k) * 68 + g * 16];
            #pragma unroll
            for (int q = 0; q < 4; q++) {
                float4 v = p[q];
                xk2[k][2*q]   = pk2(v.x, v.y);
                xk2[k][2*q+1] = pk2(v.z, v.w);
            }
        }
        #pragma unroll
        for (int fo = 0; fo < 16; fo++) {
            const int f = g * 16 + fo;
            unsigned long long a0 = 0ull, a1 = 0ull;
            const ulonglong2* wp = (const ulonglong2*)&cwt[f * 48];
            #pragma unroll
            for (int k = 0; k < 3; k++) {
                #pragma unroll
                for (int q = 0; q < 4; q++) {
                    ulonglong2 wv = wp[k * 4 + q];
                    FMA2(a0, wv.x, xk2[k][2*q]);
                    FMA2(a1, wv.y, xk2[k][2*q+1]);
                }
            }
            ADD2(a0, a0, a1);
            y[f] = hsum2(a0) + cb[f];
        }
    }

    // LayerNorm over 64 features
    float s = 0.f, s2 = 0.f;
    #pragma unroll
    for (int f = 0; f < 64; f++) { s += y[f]; s2 = fmaf(y[f], y[f], s2); }
    float mean = s * (1.f / 64.f);
    float var  = s2 * (1.f / 64.f) - mean * mean;
    float rs   = rsqrtf(var + 1e-5f);
    #pragma unroll
    for (int f = 0; f < 64; f++) y[f] = (y[f] - mean) * rs * gm[f] + bt[f];

    // pack normalized y into f32x2 pairs
    unsigned long long y2[32];
    #pragma unroll
    for (int j = 0; j < 32; j++) y2[j] = pk2(y[2*j], y[2*j+1]);

    // xg1[o] = b_ih1[o] + w_ih1[o,:] . y   (packed)
    float* outp = g_xg1 + ((size_t)b * T_ + (t0 + tid)) * G3_;
    for (int o = 0; o < 72; o++) {
        unsigned long long a0 = 0ull, a1 = 0ull;
        const ulonglong2* wp = (const ulonglong2*)&wi[o * 64];
        #pragma unroll
        for (int c = 0; c < 16; c++) {
            ulonglong2 wv = wp[c];
            FMA2(a0, wv.x, y2[2*c]);
            FMA2(a1, wv.y, y2[2*c+1]);
        }
        ADD2(a0, a0, a1);
        outp[o] = hsum2(a0) + b1[o];
    }
}

// ---------------------------------------------------------------------------
// Kernel 2: layer-pipelined GRU stack. One CTA per batch, 4 warps = 4 stages,
// ONE __syncthreads per tick. xg1 streamed into an 8-slot smem ring via
// cp.async (prefetch distance 6 ticks) so NO global-load latency ever sits on
// the critical path.
//   warp 0: GRU1 recurrent -> h1(tau)
//   warp 1: xg2 = Wih2 @ h1(tau-1)
//   warp 2: GRU2 recurrent -> h2(tau-2)
//   warp 3: FC head for step tau-3
// ---------------------------------------------------------------------------
__global__ void __launch_bounds__(128, 1) gru_kernel(
    const float* __restrict__ h1_0, const float* __restrict__ h2_0,
    const float* __restrict__ w_hh1, const float* __restrict__ b_hh1,
    const float* __restrict__ w_ih2, const float* __restrict__ w_hh2,
    const float* __restrict__ b_ih2, const float* __restrict__ b_hh2,
    const float* __restrict__ fc_w,  const float* __restrict__ fc_b,
    float* __restrict__ out_noise, float* __restrict__ out_h1,
    float* __restrict__ out_h2, int write_extra)
{
    __shared__ __align__(16) float h1buf[2][24];
    __shared__ __align__(16) float h2buf[2][24];
    __shared__ __align__(16) float xg2buf[2][72];
    __shared__ __align__(16) float xgbuf[8][72];   // cp.async ring

    const int b    = blockIdx.x;
    const int tid  = threadIdx.x;
    const int w    = tid >> 5;
    const int lane = tid & 31;

    // Per-warp register weights, packed as f32x2 pairs.
    unsigned long long wr[12], wz[12], wn[12];
    float br = 0.f, bz = 0.f, bn = 0.f;
    {
        const float* W  = (w == 0) ? w_hh1 : (w == 1) ? w_ih2 : (w == 2) ? w_hh2 : fc_w;
        const float* Bv = (w == 0) ? b_hh1 : (w == 1) ? b_ih2 : (w == 2) ? b_hh2 : fc_b;
        if (w < 3) {
            if (lane < 24) {
                const unsigned long long* Wr = (const unsigned long long*)(W + lane * 24);
                const unsigned long long* Wz = (const unsigned long long*)(W + (24 + lane) * 24);
                const unsigned long long* Wn = (const unsigned long long*)(W + (48 + lane) * 24);
                #pragma unroll
                for (int j = 0; j < 12; j++) { wr[j] = Wr[j]; wz[j] = Wz[j]; wn[j] = Wn[j]; }
                br = Bv[lane]; bz = Bv[24 + lane]; bn = Bv[48 + lane];
            }
        } else {
            const unsigned long long* Wf = (const unsigned long long*)(W + lane * 24);
            #pragma unroll
            for (int j = 0; j < 12; j++) wr[j] = Wf[j];
            br = Bv[lane];
        }
    }

    if (tid < 24) {
        h1buf[1][tid] = h1_0[b * 24 + tid];
        h2buf[1][tid] = h2_0[b * 24 + tid];
    }

    const float* xg = g_xg1 + (size_t)b * T_ * G3_;
    const unsigned xg_s = smem_u32(xgbuf);

    // prologue: prefetch steps 0..5 into slots 0..5 (6 committed groups)
    if (w == 0) {
        #pragma unroll
        for (int d = 0; d < 6; d++) {
            if (lane < 18)
                CP_ASYNC16(xg_s + (unsigned)((d * 72 + lane * 4) * 4),
                           xg + (size_t)d * 72 + lane * 4);
            CP_COMMIT();
        }
    }
    __syncthreads();

    for (int tau = 0; tau < T_ + 3; tau++) {
        const int ws = tau & 1, rs = ws ^ 1;
        if (w == 0) {
            if (tau < T_) {
                CP_WAIT(5);                         // step tau's slot is ready
                const int slot = tau & 7;
                float xr = 0.f, xz = 0.f, xn = 0.f;
                if (lane < 24) {
                    xr = xgbuf[slot][lane];
                    xz = xgbuf[slot][24 + lane];
                    xn = xgbuf[slot][48 + lane];
                }
                // issue prefetch for step tau+6 (clamped), slot (tau+6)&7
                int tp = tau + 6; if (tp > T_ - 1) tp = T_ - 1;
                if (lane < 18)
                    CP_ASYNC16(xg_s + (unsigned)(((tau + 6) & 7) * 288 + lane * 16),
                               xg + (size_t)tp * 72 + lane * 4);
                CP_COMMIT();

                if (lane < 24) {
                    unsigned long long h64[12];
                    const ulonglong2* hp = (const ulonglong2*)h1buf[rs];
                    #pragma unroll
                    for (int q = 0; q < 6; q++) { ulonglong2 v = hp[q]; h64[2*q] = v.x; h64[2*q+1] = v.y; }
                    float hold = h1buf[rs][lane];
                    unsigned long long ar = 0ull, az = 0ull, an = 0ull;
                    #pragma unroll
                    for (int j = 0; j < 12; j++) { FMA2(ar, wr[j], h64[j]); FMA2(az, wz[j], h64[j]); FMA2(an, wn[j], h64[j]); }
                    float r = fast_sigmoid(xr + hsum2(ar) + br);
                    float z = fast_sigmoid(xz + hsum2(az) + bz);
                    float n = fast_tanh(xn + r * (hsum2(an) + bn));
                    h1buf[ws][lane] = n + z * (hold - n);
                }
            }
        } else if (w == 1) {
            if (lane < 24 && tau >= 1 && tau <= T_) {
                unsigned long long h64[12];
                const ulonglong2* hp = (const ulonglong2*)h1buf[rs];  // h1(tau-1)
                #pragma unroll
                for (int q = 0; q < 6; q++) { ulonglong2 v = hp[q]; h64[2*q] = v.x; h64[2*q+1] = v.y; }
                unsigned long long ar = 0ull, az = 0ull, an = 0ull;
                #pragma unroll
                for (int j = 0; j < 12; j++) { FMA2(ar, wr[j], h64[j]); FMA2(az, wz[j], h64[j]); FMA2(an, wn[j], h64[j]); }
                xg2buf[ws][lane]      = hsum2(ar) + br;
                xg2buf[ws][24 + lane] = hsum2(az) + bz;
                xg2buf[ws][48 + lane] = hsum2(an) + bn;
            }
        } else if (w == 2) {
            if (lane < 24 && tau >= 2 && tau <= T_ + 1) {
                unsigned long long h64[12];
                const ulonglong2* hp = (const ulonglong2*)h2buf[rs];  // h2(tau-3)
                #pragma unroll
                for (int q = 0; q < 6; q++) { ulonglong2 v = hp[q]; h64[2*q] = v.x; h64[2*q+1] = v.y; }
                float hold = h2buf[rs][lane];
                float xr = xg2buf[rs][lane];
                float xz = xg2buf[rs][24 + lane];
                float xn = xg2buf[rs][48 + lane];
                unsigned long long ar = 0ull, az = 0ull, an = 0ull;
                #pragma unroll
                for (int j = 0; j < 12; j++) { FMA2(ar, wr[j], h64[j]); FMA2(az, wz[j], h64[j]); FMA2(an, wn[j], h64[j]); }
                float r = fast_sigmoid(xr + hsum2(ar) + br);
                float z = fast_sigmoid(xz + hsum2(az) + bz);
                float n = fast_tanh(xn + r * (hsum2(an) + bn));
                h2buf[ws][lane] = n + z * (hold - n);
            }
        } else {
            if (tau >= 3) {
                unsigned long long h64[12];
                const ulonglong2* hp = (const ulonglong2*)h2buf[rs];  // h2(tau-3)
                #pragma unroll
                for (int q = 0; q < 6; q++) { ulonglong2 v = hp[q]; h64[2*q] = v.x; h64[2*q+1] = v.y; }
                unsigned long long a = 0ull;
                #pragma unroll
                for (int j = 0; j < 12; j++) FMA2(a, wr[j], h64[j]);
                out_noise[((size_t)b * T_ + (tau - 3)) * 32 + lane] = hsum2(a) + br;
            }
        }
        __syncthreads();
    }

    if (write_extra && tid < 24) {
        out_h1[b * 24 + tid] = h1buf[(T_ - 1) & 1][tid];
        out_h2[b * 24 + tid] = h2buf[(T_ + 1) & 1][tid];
    }
}

// ---------------------------------------------------------------------------
// Kernel 3: confidence = 1/(1+std(noise, ddof=1)) over last dim (32).
// ---------------------------------------------------------------------------
__global__ void __launch_bounds__(256) conf_kernel(
    const float* __restrict__ noise, float* __restrict__ conf)
{
    const size_t row = (size_t)blockIdx.x * 8 + (threadIdx.x >> 5);
    const int lane = threadIdx.x & 31;
    float o = noise[row * 32 + lane];
    float su = o, sq = o * o;
    #pragma unroll
    for (int m = 16; m >= 1; m >>= 1) {
        su += __shfl_xor_sync(0xffffffffu, su, m);
        sq += __shfl_xor_sync(0xffffffffu, sq, m);
    }
    if (lane == 0) {
        float ss = fmaxf(sq - su * su * (1.f / 32.f), 0.f);
        float sd = sqrtf(ss * (1.f / 31.f));   // ddof = 1
        conf[row] = __fdividef(1.f, 1.f + sd);
    }
}

// ---------------------------------------------------------------------------
extern "C" void kernel_launch(void* const* d_in, const int* in_sizes, int n_in,
                              void* d_out, int out_size)
{
    const float* x      = (const float*)d_in[0];
    const float* h1     = (const float*)d_in[1];
    const float* h2     = (const float*)d_in[2];
    const float* conv_w = (const float*)d_in[3];
    const float* conv_b = (const float*)d_in[4];
    const float* gamma  = (const float*)d_in[5];
    const float* beta   = (const float*)d_in[6];
    const float* w_ih1  = (const float*)d_in[7];
    const float* w_hh1  = (const float*)d_in[8];
    const float* b_ih1  = (const float*)d_in[9];
    const float* b_hh1  = (const float*)d_in[10];
    const float* w_ih2  = (const float*)d_in[11];
    const float* w_hh2  = (const float*)d_in[12];
    const float* b_ih2  = (const float*)d_in[13];
    const float* b_hh2  = (const float*)d_in[14];
    const float* fc_w   = (const float*)d_in[15];
    const float* fc_b   = (const float*)d_in[16];

    float* out = (float*)d_out;
    const size_t NOISE = (size_t)B_ * T_ * 32;
    const size_t FULL  = NOISE + 2 * (size_t)B_ * HID_ + (size_t)B_ * T_;
    int extra = ((size_t)out_size >= FULL) ? 1 : 0;
    float* o_h1   = out + NOISE;
    float* o_h2   = o_h1 + B_ * HID_;
    float* o_conf = o_h2 + B_ * HID_;

    const int SMEM = (130 * 68 + 3072 + 64 * 3 + 4608 + 72) * (int)sizeof(float);
    cudaFuncSetAttribute(pre_kernel, cudaFuncAttributeMaxDynamicSharedMemorySize, SMEM);

    pre_kernel<<<dim3(T_ / 128, B_), 128, SMEM>>>(x, conv_w, conv_b, gamma, beta,
                                                  w_ih1, b_ih1);
    gru_kernel<<<B_, 128>>>(h1, h2, w_hh1, b_hh1, w_ih2, w_hh2, b_ih2, b_hh2,
                            fc_w, fc_b, out, o_h1, o_h2, extra);
    if (extra) conf_kernel<<<(B_ * T_) / 8, 256>>>(out, o_conf);
}

// round 8
// speedup vs baseline: 2.4480x; 1.2956x over previous
#include <cuda_runtime.h>

#define B_    128
#define T_    4096
#define FEAT_ 64
#define HID_  24
#define G3_   72   // 3 * HID
#define NTICK (T_ / 2 + 3)   // 2051 ticks, 2 timesteps each

// Scratch for precomputed GRU1 input gates: [B, T, 72]  (~151 MB)
__device__ float g_xg1[(size_t)B_ * T_ * G3_];

// ---------------------------------------------------------------------------
// Packed f32x2 helpers (PTX 8.6, sm_100+)
// ---------------------------------------------------------------------------
#define FMA2(acc, a, b) \
    asm("fma.rn.f32x2 %0, %1, %2, %0;" : "+l"(acc) : "l"(a), "l"(b))
#define ADD2(d, a, b) \
    asm("add.rn.f32x2 %0, %1, %2;" : "=l"(d) : "l"(a), "l"(b))

__device__ __forceinline__ unsigned long long pk2(float lo, float hi) {
    unsigned long long r;
    asm("mov.b64 %0, {%1, %2};" : "=l"(r) : "f"(lo), "f"(hi));
    return r;
}
__device__ __forceinline__ float hsum2(unsigned long long v) {
    float lo, hi;
    asm("mov.b64 {%0, %1}, %2;" : "=f"(lo), "=f"(hi) : "l"(v));
    return lo + hi;
}
__device__ __forceinline__ float fast_sigmoid(float v) {
    return __fdividef(1.f, 1.f + __expf(-v));
}
__device__ __forceinline__ float fast_tanh(float v) {
    return 1.f - __fdividef(2.f, __expf(2.f * v) + 1.f);
}
__device__ __forceinline__ unsigned smem_u32(const void* p) {
    unsigned a;
    asm("{ .reg .u64 t; cvta.to.shared.u64 t, %1; cvt.u32.u64 %0, t; }"
        : "=r"(a) : "l"(p));
    return a;
}
#define CP_ASYNC16(dst_u32, src_ptr) \
    asm volatile("cp.async.cg.shared.global [%0], [%1], 16;" \
                 :: "r"(dst_u32), "l"(src_ptr))
#define CP_COMMIT()  asm volatile("cp.async.commit_group;")
#define CP_WAIT(N)   asm volatile("cp.async.wait_group %0;" :: "n"(N))

// ---------------------------------------------------------------------------
// Kernel 1: grouped causal conv (k=3, groups=4) + LayerNorm + xg1 GEMM
// grid: (T/128, B), block: 128 threads (one thread per timestep)
// GEMM is 4-output blocked for ILP; outputs stored as float4.
// ---------------------------------------------------------------------------
__global__ void __launch_bounds__(128, 3) pre_kernel(
    const float* __restrict__ x,       // [B, T, 64]
    const float* __restrict__ conv_w,  // [64, 16, 3]
    const float* __restrict__ conv_b,  // [64]
    const float* __restrict__ gamma,   // [64]
    const float* __restrict__ beta,    // [64]
    const float* __restrict__ w_ih1,   // [72, 64]
    const float* __restrict__ b_ih1)   // [72]
{
    extern __shared__ float sm[];
    float* xs  = sm;                 // 130 * 68 (rows padded to 68 floats)
    float* cwt = xs + 130 * 68;      // 3072, transposed to [f][k][c]
    float* cb  = cwt + 3072;         // 64
    float* gm  = cb + 64;            // 64
    float* bt  = gm + 64;            // 64
    float* wi  = bt + 64;            // 4608
    float* b1  = wi + 4608;          // 72

    const int b   = blockIdx.y;
    const int t0  = blockIdx.x * 128;
    const int tid = threadIdx.x;

    const float* xb = x + (size_t)b * T_ * FEAT_;
    for (int i = tid; i < 130 * 64; i += 128) {
        int r = i >> 6, f = i & 63;
        int t = t0 - 2 + r;
        xs[r * 68 + f] = (t >= 0) ? xb[(size_t)t * 64 + f] : 0.f;
    }
    for (int i = tid; i < 3072; i += 128) {
        int f = i / 48, r = i % 48, k = r >> 4, c = r & 15;
        cwt[i] = conv_w[f * 48 + c * 3 + k];
    }
    for (int i = tid; i < 4608; i += 128) wi[i] = w_ih1[i];
    if (tid < 64) { cb[tid] = conv_b[tid]; gm[tid] = gamma[tid]; bt[tid] = beta[tid]; }
    if (tid < 72) b1[tid] = b_ih1[tid];
    __syncthreads();

    float y[64];
    #pragma unroll
    for (int g = 0; g < 4; g++) {
        unsigned long long xk2[3][8];
        #pragma unroll
        for (int k = 0; k < 3; k++) {
            const float4* p = (const float4*)&xs[(tid + k) * 68 + g * 16];
            #pragma unroll
            for (int q = 0; q < 4; q++) {
                float4 v = p[q];
                xk2[k][2*q]   = pk2(v.x, v.y);
                xk2[k][2*q+1] = pk2(v.z, v.w);
            }
        }
        #pragma unroll
        for (int fo = 0; fo < 16; fo++) {
            const int f = g * 16 + fo;
            unsigned long long a0 = 0ull, a1 = 0ull;
            const ulonglong2* wp = (const ulonglong2*)&cwt[f * 48];
            #pragma unroll
            for (int k = 0; k < 3; k++) {
                #pragma unroll
                for (int q = 0; q < 4; q++) {
                    ulonglong2 wv = wp[k * 4 + q];
                    FMA2(a0, wv.x, xk2[k][2*q]);
                    FMA2(a1, wv.y, xk2[k][2*q+1]);
                }
            }
            ADD2(a0, a0, a1);
            y[f] = hsum2(a0) + cb[f];
        }
    }

    // LayerNorm over 64 features
    float s = 0.f, s2 = 0.f;
    #pragma unroll
    for (int f = 0; f < 64; f++) { s += y[f]; s2 = fmaf(y[f], y[f], s2); }
    float mean = s * (1.f / 64.f);
    float var  = s2 * (1.f / 64.f) - mean * mean;
    float rs   = rsqrtf(var + 1e-5f);
    #pragma unroll
    for (int f = 0; f < 64; f++) y[f] = (y[f] - mean) * rs * gm[f] + bt[f];

    unsigned long long y2[32];
    #pragma unroll
    for (int j = 0; j < 32; j++) y2[j] = pk2(y[2*j], y[2*j+1]);

    // xg1[o] = b_ih1[o] + w_ih1[o,:] . y  — 4 outputs per iteration, float4 store
    float* outp = g_xg1 + ((size_t)b * T_ + (t0 + tid)) * G3_;
    for (int o4 = 0; o4 < 18; o4++) {
        const int o = o4 * 4;
        unsigned long long a0 = 0ull, a1 = 0ull, e0 = 0ull, e1 = 0ull;
        unsigned long long c0 = 0ull, c1 = 0ull, d0 = 0ull, d1 = 0ull;
        const ulonglong2* w0 = (const ulonglong2*)&wi[(o + 0) * 64];
        const ulonglong2* w1 = (const ulonglong2*)&wi[(o + 1) * 64];
        const ulonglong2* w2 = (const ulonglong2*)&wi[(o + 2) * 64];
        const ulonglong2* w3 = (const ulonglong2*)&wi[(o + 3) * 64];
        #pragma unroll
        for (int c = 0; c < 16; c++) {
            ulonglong2 v0 = w0[c], v1 = w1[c], v2 = w2[c], v3 = w3[c];
            FMA2(a0, v0.x, y2[2*c]); FMA2(a1, v0.y, y2[2*c+1]);
            FMA2(e0, v1.x, y2[2*c]); FMA2(e1, v1.y, y2[2*c+1]);
            FMA2(c0, v2.x, y2[2*c]); FMA2(c1, v2.y, y2[2*c+1]);
            FMA2(d0, v3.x, y2[2*c]); FMA2(d1, v3.y, y2[2*c+1]);
        }
        ADD2(a0, a0, a1); ADD2(e0, e0, e1); ADD2(c0, c0, c1); ADD2(d0, d0, d1);
        float4 res;
        res.x = hsum2(a0) + b1[o + 0];
        res.y = hsum2(e0) + b1[o + 1];
        res.z = hsum2(c0) + b1[o + 2];
        res.w = hsum2(d0) + b1[o + 3];
        ((float4*)outp)[o4] = res;
    }
}

// ---------------------------------------------------------------------------
// Kernel 2: layer-pipelined GRU stack, TWO timesteps per tick.
// One CTA per batch, 4 warps = 4 stages, ONE __syncthreads per tick:
//   warp 0: GRU1  -> h1(2tau), h1(2tau+1)
//   warp 1: xg2 = Wih2 @ h1  for the two steps of tick tau-1
//   warp 2: GRU2  -> h2 for the two steps of tick tau-2
//   warp 3: FC head for the two steps of tick tau-3
// xg1 streamed via cp.async ring (8 slots, 2 steps per commit group, depth 3).
// ---------------------------------------------------------------------------
__device__ __forceinline__ void load_h64(unsigned long long h64[12], const float* buf) {
    const ulonglong2* hp = (const ulonglong2*)buf;
    #pragma unroll
    for (int q = 0; q < 6; q++) { ulonglong2 v = hp[q]; h64[2*q] = v.x; h64[2*q+1] = v.y; }
}
__device__ __forceinline__ void gemv3(float& gr, float& gz, float& gn,
    const unsigned long long* wr, const unsigned long long* wz, const unsigned long long* wn,
    const unsigned long long h64[12], float br, float bz, float bn) {
    unsigned long long ar = pk2(br, 0.f), az = pk2(bz, 0.f), an = pk2(bn, 0.f);
    #pragma unroll
    for (int j = 0; j < 12; j++) {
        FMA2(ar, wr[j], h64[j]); FMA2(az, wz[j], h64[j]); FMA2(an, wn[j], h64[j]);
    }
    gr = hsum2(ar); gz = hsum2(az); gn = hsum2(an);
}

__global__ void __launch_bounds__(128, 1) gru_kernel(
    const float* __restrict__ h1_0, const float* __restrict__ h2_0,
    const float* __restrict__ w_hh1, const float* __restrict__ b_hh1,
    const float* __restrict__ w_ih2, const float* __restrict__ w_hh2,
    const float* __restrict__ b_ih2, const float* __restrict__ b_hh2,
    const float* __restrict__ fc_w,  const float* __restrict__ fc_b,
    float* __restrict__ out_noise, float* __restrict__ out_h1,
    float* __restrict__ out_h2, int write_extra)
{
    __shared__ __align__(16) float h1pub[2][2][24];   // [parity][step][lane]
    __shared__ __align__(16) float h2pub[2][2][24];
    __shared__ __align__(16) float xg2buf[2][2][72];
    __shared__ __align__(16) float xgbuf[8][72];      // cp.async ring

    const int b    = blockIdx.x;
    const int tid  = threadIdx.x;
    const int w    = tid >> 5;
    const int lane = tid & 31;

    // Per-warp register weights, packed as f32x2 pairs over the input dim.
    unsigned long long wr[12], wz[12], wn[12];
    float br = 0.f, bz = 0.f, bn = 0.f;
    {
        const float* W  = (w == 0) ? w_hh1 : (w == 1) ? w_ih2 : (w == 2) ? w_hh2 : fc_w;
        const float* Bv = (w == 0) ? b_hh1 : (w == 1) ? b_ih2 : (w == 2) ? b_hh2 : fc_b;
        if (w < 3) {
            if (lane < 24) {
                const unsigned long long* Wr = (const unsigned long long*)(W + lane * 24);
                const unsigned long long* Wz = (const unsigned long long*)(W + (24 + lane) * 24);
                const unsigned long long* Wn = (const unsigned long long*)(W + (48 + lane) * 24);
                #pragma unroll
                for (int j = 0; j < 12; j++) { wr[j] = Wr[j]; wz[j] = Wz[j]; wn[j] = Wn[j]; }
                br = Bv[lane]; bz = Bv[24 + lane]; bn = Bv[48 + lane];
            }
        } else {
            const unsigned long long* Wf = (const unsigned long long*)(W + lane * 24);
            #pragma unroll
            for (int j = 0; j < 12; j++) wr[j] = Wf[j];
            br = Bv[lane];
        }
    }

    if (tid < 24) {
        h1pub[1][1][tid] = h1_0[b * 24 + tid];
        h2pub[1][1][tid] = h2_0[b * 24 + tid];
    }

    const float* xg = g_xg1 + (size_t)b * T_ * G3_;
    const unsigned xg_s = smem_u32(xgbuf);

    // prologue: steps 0..5 into slots 0..5, 3 commit groups (2 steps each)
    if (w == 0) {
        #pragma unroll
        for (int g = 0; g < 3; g++) {
            if (lane < 18) {
                CP_ASYNC16(xg_s + (unsigned)((2*g) * 288 + lane * 16),
                           xg + (size_t)(2*g) * 72 + lane * 4);
                CP_ASYNC16(xg_s + (unsigned)((2*g+1) * 288 + lane * 16),
                           xg + (size_t)(2*g+1) * 72 + lane * 4);
            }
            CP_COMMIT();
        }
    }
    __syncthreads();

    for (int tau = 0; tau < NTICK; tau++) {
        const int ws = tau & 1, rs = ws ^ 1;
        if (w == 0) {
            if (tau < T_ / 2) {
                CP_WAIT(2);
                const int sa = (2 * tau) & 7, sb = sa + 1;
                float xra = 0, xza = 0, xna = 0, xrb = 0, xzb = 0, xnb = 0;
                float h1a = 0.f;
                if (lane < 24) {
                    xra = xgbuf[sa][lane]; xza = xgbuf[sa][24+lane]; xna = xgbuf[sa][48+lane];
                    xrb = xgbuf[sb][lane]; xzb = xgbuf[sb][24+lane]; xnb = xgbuf[sb][48+lane];
                    unsigned long long h64[12];
                    load_h64(h64, h1pub[rs][1]);
                    float hold = h1pub[rs][1][lane];
                    float gr, gz, gn;
                    gemv3(gr, gz, gn, wr, wz, wn, h64, br, bz, bn);
                    float r = fast_sigmoid(xra + gr);
                    float z = fast_sigmoid(xza + gz);
                    float n = fast_tanh(xna + r * gn);
                    h1a = n + z * (hold - n);
                    h1pub[ws][0][lane] = h1a;
                }
                __syncwarp();
                if (lane < 24) {
                    unsigned long long h64[12];
                    load_h64(h64, h1pub[ws][0]);
                    float gr, gz, gn;
                    gemv3(gr, gz, gn, wr, wz, wn, h64, br, bz, bn);
                    float r = fast_sigmoid(xrb + gr);
                    float z = fast_sigmoid(xzb + gz);
                    float n = fast_tanh(xnb + r * gn);
                    h1pub[ws][1][lane] = n + z * (h1a - n);
                }
                // prefetch steps 2tau+6, 2tau+7 (slot index from unclamped step)
                int pa = 2 * tau + 6, pb = pa + 1;
                const unsigned sA = (unsigned)(pa & 7) * 288, sB = (unsigned)(pb & 7) * 288;
                if (pa > T_ - 1) pa = T_ - 1;
                if (pb > T_ - 1) pb = T_ - 1;
                if (lane < 18) {
                    CP_ASYNC16(xg_s + sA + lane * 16, xg + (size_t)pa * 72 + lane * 4);
                    CP_ASYNC16(xg_s + sB + lane * 16, xg + (size_t)pb * 72 + lane * 4);
                }
                CP_COMMIT();
            }
        } else if (w == 1) {
            if (lane < 24 && tau >= 1 && tau <= T_ / 2) {
                #pragma unroll
                for (int s = 0; s < 2; s++) {
                    unsigned long long h64[12];
                    load_h64(h64, h1pub[rs][s]);
                    float gr, gz, gn;
                    gemv3(gr, gz, gn, wr, wz, wn, h64, br, bz, bn);
                    xg2buf[ws][s][lane]      = gr;
                    xg2buf[ws][s][24 + lane] = gz;
                    xg2buf[ws][s][48 + lane] = gn;
                }
            }
        } else if (w == 2) {
            if (tau >= 2 && tau <= T_ / 2 + 1) {
                float h2a = 0.f;
                if (lane < 24) {
                    unsigned long long h64[12];
                    load_h64(h64, h2pub[rs][1]);
                    float hold = h2pub[rs][1][lane];
                    float gr, gz, gn;
                    gemv3(gr, gz, gn, wr, wz, wn, h64, br, bz, bn);
                    float r = fast_sigmoid(xg2buf[rs][0][lane] + gr);
                    float z = fast_sigmoid(xg2buf[rs][0][24+lane] + gz);
                    float n = fast_tanh(xg2buf[rs][0][48+lane] + r * gn);
                    h2a = n + z * (hold - n);
                    h2pub[ws][0][lane] = h2a;
                }
                __syncwarp();
                if (lane < 24) {
                    unsigned long long h64[12];
                    load_h64(h64, h2pub[ws][0]);
                    float gr, gz, gn;
                    gemv3(gr, gz, gn, wr, wz, wn, h64, br, bz, bn);
                    float r = fast_sigmoid(xg2buf[rs][1][lane] + gr);
                    float z = fast_sigmoid(xg2buf[rs][1][24+lane] + gz);
                    float n = fast_tanh(xg2buf[rs][1][48+lane] + r * gn);
                    h2pub[ws][1][lane] = n + z * (h2a - n);
                }
            }
        } else {
            if (tau >= 3) {
                const size_t t0o = (size_t)b * T_ + 2 * (tau - 3);
                #pragma unroll
                for (int s = 0; s < 2; s++) {
                    unsigned long long h64[12];
                    load_h64(h64, h2pub[rs][s]);
                    unsigned long long a = pk2(br, 0.f);
                    #pragma unroll
                    for (int j = 0; j < 12; j++) FMA2(a, wr[j], h64[j]);
                    out_noise[(t0o + s) * 32 + lane] = hsum2(a);
                }
            }
        }
        __syncthreads();
    }

    if (write_extra && tid < 24) {
        out_h1[b * 24 + tid] = h1pub[1][1][tid];   // h1(4095), written at tick 2047
        out_h2[b * 24 + tid] = h2pub[1][1][tid];   // h2(4095), written at tick 2049
    }
}

// ---------------------------------------------------------------------------
// Kernel 3: confidence = 1/(1+std(noise, ddof=1)) over last dim (32).
// ---------------------------------------------------------------------------
__global__ void __launch_bounds__(256) conf_kernel(
    const float* __restrict__ noise, float* __restrict__ conf)
{
    const size_t row = (size_t)blockIdx.x * 8 + (threadIdx.x >> 5);
    const int lane = threadIdx.x & 31;
    float o = noise[row * 32 + lane];
    float su = o, sq = o * o;
    #pragma unroll
    for (int m = 16; m >= 1; m >>= 1) {
        su += __shfl_xor_sync(0xffffffffu, su, m);
        sq += __shfl_xor_sync(0xffffffffu, sq, m);
    }
    if (lane == 0) {
        float ss = fmaxf(sq - su * su * (1.f / 32.f), 0.f);
        float sd = sqrtf(ss * (1.f / 31.f));   // ddof = 1
        conf[row] = __fdividef(1.f, 1.f + sd);
    }
}

// ---------------------------------------------------------------------------
extern "C" void kernel_launch(void* const* d_in, const int* in_sizes, int n_in,
                              void* d_out, int out_size)
{
    const float* x      = (const float*)d_in[0];
    const float* h1     = (const float*)d_in[1];
    const float* h2     = (const float*)d_in[2];
    const float* conv_w = (const float*)d_in[3];
    const float* conv_b = (const float*)d_in[4];
    const float* gamma  = (const float*)d_in[5];
    const float* beta   = (const float*)d_in[6];
    const float* w_ih1  = (const float*)d_in[7];
    const float* w_hh1  = (const float*)d_in[8];
    const float* b_ih1  = (const float*)d_in[9];
    const float* b_hh1  = (const float*)d_in[10];
    const float* w_ih2  = (const float*)d_in[11];
    const float* w_hh2  = (const float*)d_in[12];
    const float* b_ih2  = (const float*)d_in[13];
    const float* b_hh2  = (const float*)d_in[14];
    const float* fc_w   = (const float*)d_in[15];
    const float* fc_b   = (const float*)d_in[16];

    float* out = (float*)d_out;
    const size_t NOISE = (size_t)B_ * T_ * 32;
    const size_t FULL  = NOISE + 2 * (size_t)B_ * HID_ + (size_t)B_ * T_;
    int extra = ((size_t)out_size >= FULL) ? 1 : 0;
    float* o_h1   = out + NOISE;
    float* o_h2   = o_h1 + B_ * HID_;
    float* o_conf = o_h2 + B_ * HID_;

    const int SMEM = (130 * 68 + 3072 + 64 * 3 + 4608 + 72) * (int)sizeof(float);
    cudaFuncSetAttribute(pre_kernel, cudaFuncAttributeMaxDynamicSharedMemorySize, SMEM);

    pre_kernel<<<dim3(T_ / 128, B_), 128, SMEM>>>(x, conv_w, conv_b, gamma, beta,
                                                  w_ih1, b_ih1);
    gru_kernel<<<B_, 128>>>(h1, h2, w_hh1, b_hh1, w_ih2, w_hh2, b_ih2, b_hh2,
                            fc_w, fc_b, out, o_h1, o_h2, extra);
    if (extra) conf_kernel<<<(B_ * T_) / 8, 256>>>(out, o_conf);
}